// round 12
// baseline (speedup 1.0000x reference)
#include <cuda_runtime.h>
#include <cuda_fp16.h>

#define Bq 4
#define Cc 32
#define Tt 1024
#define Uu 32
#define Hh 128
#define NCHK 4                  // 256-j chunks

// Scratch — device globals (no allocations allowed).
__device__ float    g_qp[Bq * Tt * Uu];            // q + bh, (B,T,U) f32
__device__ unsigned g_kh_u[Bq * Uu * Tt / 2];      // k as f16, (B,U,T)
__device__ unsigned g_xh_u[Bq * Cc * Tt / 2];      // x as f16, (B,C,T)

__device__ __forceinline__ __half2 tanh2(__half2 x) {
    unsigned xi = *reinterpret_cast<unsigned*>(&x), ri;
    asm("tanh.approx.f16x2 %0, %1;" : "=r"(ri) : "r"(xi));
    return *reinterpret_cast<__half2*>(&ri);
}
__device__ __forceinline__ __half2 u2h2(unsigned u) { return *reinterpret_cast<__half2*>(&u); }
__device__ __forceinline__ unsigned h22u(__half2 h) { return *reinterpret_cast<unsigned*>(&h); }

// ---------------------------------------------------------------------------
// k_prep (R8, proven): 8 tokens/block, grid = B*(T/8) = 512, 256 threads.
// ---------------------------------------------------------------------------
__global__ void __launch_bounds__(256) k_prep(const float* __restrict__ x,
                                              const float* __restrict__ Wt,
                                              const float* __restrict__ Wx,
                                              const float* __restrict__ bh) {
    __shared__ float xs[Cc][9];
    __shared__ float Wts[Cc][33];
    __shared__ float Wxs[Cc][33];
    __shared__ float bhs[Uu];
    __shared__ __half kts[Uu][10];

    int b  = blockIdx.x >> 7;
    int t0 = (blockIdx.x & 127) * 8;
    int tid = threadIdx.x, w = tid >> 5, lane = tid & 31;

    {
        int c = tid >> 3, tl = tid & 7;
        xs[c][tl] = x[(size_t)b * Cc * Tt + (size_t)c * Tt + t0 + tl];
    }
    for (int i = tid; i < Cc * Uu; i += 256) {
        int c = i >> 5, u = i & 31;
        Wts[c][u] = Wt[i];
        Wxs[c][u] = Wx[i];
    }
    if (tid < Uu) bhs[tid] = bh[tid];
    __syncthreads();

    {
        int tl = w, u = lane;
        float accq = bhs[u], acck = 0.f;
        #pragma unroll
        for (int c = 0; c < Cc; c++) {
            float xv = xs[c][tl];
            accq += xv * Wts[c][u];
            acck += xv * Wxs[c][u];
        }
        g_qp[((size_t)b * Tt + t0 + tl) * Uu + u] = accq;
        kts[u][tl] = __float2half(acck);
    }
    __syncthreads();

    if (tid < 128) {
        int r = tid >> 2, g = tid & 3;
        __half* kh = (__half*)g_kh_u;
        __half2 kv = __halves2half2(kts[r][2 * g], kts[r][2 * g + 1]);
        *(unsigned*)(kh + ((size_t)b * Uu + r) * Tt + t0 + 2 * g) = h22u(kv);
        __half* xh = (__half*)g_xh_u;
        __half2 xv = __floats2half2_rn(xs[r][2 * g], xs[r][2 * g + 1]);
        *(unsigned*)(xh + ((size_t)b * Cc + r) * Tt + t0 + 2 * g) = h22u(xv);
    }
}

// ---------------------------------------------------------------------------
// k_fused v3 (j-split): 8 rows/block, 256 threads, grid = B*(T/8) = 512.
// warp (wp = w&3, jh = w>>2) owns rows {2wp, 2wp+1}, j-half jh.
// ---------------------------------------------------------------------------
#define OFF_K    0                           // half2 khs[32][128] 16384 | x-tile | W1T overlay
#define OFF_E    16384                       // half2 es[8][512]   16384 | W2p overlay
#define OFF_WA   32768                       // half2 was[32]        128 (dead by FF)
#define OFF_Q    32896                       // float qsm[8*33]     1056 (dead by FF)
#define OFF_YS   33952                       // float ys[8*33]      1056
#define OFF_H1   35008                       // float h1s[8*132]    4224
#define OFF_B1   39232                       // float b1s[128]       512
#define OFF_B2   39744                       // float b2s[32]        128
#define OFF_G2   39872                       // float g2s[32]        128
#define OFF_BE2  40000                       // float be2s[32]       128
#define OFF_VS   40128                       // float vsh[8*33]     1056
#define OFF_SS   41184                       // float ssh[8]          32
#define OFF_MS   41216                       // float msh[8]          32
#define SMEM_FUSED 41248

__global__ void __launch_bounds__(256, 2) k_fused(const float* __restrict__ x,
                                                  float* __restrict__ a_out,
                                                  const float* __restrict__ Wa,
                                                  const float* __restrict__ ba,
                                                  const float* __restrict__ g1,
                                                  const float* __restrict__ be1,
                                                  const float* __restrict__ W1,
                                                  const float* __restrict__ b1,
                                                  const float* __restrict__ W2,
                                                  const float* __restrict__ b2,
                                                  const float* __restrict__ g2,
                                                  const float* __restrict__ be2,
                                                  float* __restrict__ y2) {
    extern __shared__ char dyn[];
    __half2* khs  = (__half2*)(dyn + OFF_K);    // [32][128]
    __half2* es   = (__half2*)(dyn + OFF_E);    // [8][512]
    __half2* was  = (__half2*)(dyn + OFF_WA);
    float* qsm  = (float*)(dyn + OFF_Q);
    float* W1T  = (float*)(dyn + OFF_K);        // FF overlay
    float* W2p  = (float*)(dyn + OFF_K + 16512);
    float* ys   = (float*)(dyn + OFF_YS);
    float* h1s  = (float*)(dyn + OFF_H1);
    float* b1s  = (float*)(dyn + OFF_B1);
    float* b2s  = (float*)(dyn + OFF_B2);
    float* g2s  = (float*)(dyn + OFF_G2);
    float* be2s = (float*)(dyn + OFF_BE2);
    float* vsh  = (float*)(dyn + OFF_VS);
    float* ssh  = (float*)(dyn + OFF_SS);
    float* msh  = (float*)(dyn + OFF_MS);

    int b  = blockIdx.x >> 7;
    int t0 = (blockIdx.x & 127) * 8;
    int tid = threadIdx.x, w = tid >> 5, lane = tid & 31;
    int wp = w & 3, jh = w >> 2;
    int rA = 2 * wp, rB = rA + 1;

    // ---- staging ----
    for (int i = tid; i < 8 * Uu; i += 256) {
        int r = i >> 5, u = i & 31;
        qsm[r * 33 + u] = g_qp[((size_t)b * Tt + t0 + r) * Uu + u];
    }
    if (tid < Uu) was[tid] = __float2half2_rn(Wa[tid]);
    if (tid < Hh) b1s[tid] = b1[tid];
    if (tid < Cc) { b2s[tid] = b2[tid]; g2s[tid] = g2[tid]; be2s[tid] = be2[tid]; }
    __syncthreads();

    __half2 qA[Uu], qB[Uu];
    #pragma unroll
    for (int u = 0; u < Uu; u++) {
        qA[u] = __float2half2_rn(qsm[rA * 33 + u]);
        qB[u] = __float2half2_rn(qsm[rB * 33 + u]);
    }
    __half2 ba2  = __float2half2_rn(ba[0]);
    __half2 mA2  = __float2half2_rn(-60000.f), mB2 = mA2;
    __half2 z2   = __float2half2_rn(0.f);
    __half2 one2 = __float2half2_rn(1.f);
    __half2 ca2  = __float2half2_rn(-1.f / 3.f);
    __half2 cb2  = __float2half2_rn(2.f / 15.f);

    const uint4* kb4 = (const uint4*)g_kh_u + (size_t)b * (Uu * Tt / 8);

    // ---- Phase A: e for rows rA,rB over this warp's j-half ----
    for (int ch = 0; ch < NCHK; ch++) {
        __syncthreads();
        #pragma unroll
        for (int k = 0; k < 4; k++) {
            int idx = tid + k * 256;
            int r = idx >> 5, g = idx & 31;
            ((uint4*)khs)[idx] = kb4[r * 128 + ch * 32 + g];
        }
        __syncthreads();

        #pragma unroll
        for (int jt2 = 0; jt2 < 2; jt2++) {
            int pj = (jh * 2 + jt2) * 32 + lane;
            __half2 a0 = z2, a1 = z2, b0 = z2, b1h = z2;
            #pragma unroll
            for (int u = 0; u < Uu; u += 2) {
                __half2 k0 = khs[u * 128 + pj], k1 = khs[(u + 1) * 128 + pj];
                __half2 w0 = was[u], w1 = was[u + 1];
                a0 = __hfma2(w0, tanh2(__hadd2(qA[u], k0)), a0);
                b0 = __hfma2(w0, tanh2(__hadd2(qB[u], k0)), b0);
                __half2 xpA = __hadd2(qA[u + 1], k1);
                __half2 x2A = __hmul2(xpA, xpA);
                __half2 tpA = __hfma2(x2A, cb2, ca2);
                tpA = __hfma2(x2A, tpA, one2);
                a1 = __hfma2(w1, __hmul2(xpA, tpA), a1);
                __half2 xpB = __hadd2(qB[u + 1], k1);
                __half2 x2B = __hmul2(xpB, xpB);
                __half2 tpB = __hfma2(x2B, cb2, ca2);
                tpB = __hfma2(x2B, tpB, one2);
                b1h = __hfma2(w1, __hmul2(xpB, tpB), b1h);
            }
            __half2 eA2 = __hadd2(__hadd2(a0, a1), ba2);
            __half2 eB2 = __hadd2(__hadd2(b0, b1h), ba2);
            mA2 = __hmax2(mA2, eA2);
            mB2 = __hmax2(mB2, eB2);
            es[rA * 512 + ch * 128 + pj] = eA2;
            es[rB * 512 + ch * 128 + pj] = eB2;
        }
    }

    float mA = fmaxf(__low2float(mA2), __high2float(mA2));
    float mB = fmaxf(__low2float(mB2), __high2float(mB2));
    #pragma unroll
    for (int off = 16; off; off >>= 1) {
        mA = fmaxf(mA, __shfl_xor_sync(0xffffffffu, mA, off));
        mB = fmaxf(mB, __shfl_xor_sync(0xffffffffu, mB, off));
    }

    // ---- Phase B: s + unnormalized v. lanes 0-15 = row rA, 16-31 = row rB;
    //      each lane handles one uint4 (8 e's) of its row's j-half per chunk.
    int half = lane >> 4, li = lane & 15;
    int r = half ? rB : rA;
    float s = 0.f;
    __half2 v2[Cc];
    #pragma unroll
    for (int c = 0; c < Cc; c++) v2[c] = z2;

    const uint4* xsrc = (const uint4*)g_xh_u + (size_t)b * (Cc * Tt / 8);
    __half2* xh2s = khs;   // overlay

    for (int ch = 0; ch < NCHK; ch++) {
        __syncthreads();
        #pragma unroll
        for (int k = 0; k < 4; k++) {
            int idx = tid + k * 256;
            int rr = idx >> 5, g = idx & 31;
            ((uint4*)xh2s)[idx] = xsrc[rr * 128 + ch * 32 + g];
        }
        __syncthreads();

        uint4 ev = ((const uint4*)es)[r * 128 + ch * 32 + jh * 16 + li];
        unsigned eu[4] = {ev.x, ev.y, ev.z, ev.w};
        __half2 p[4];
        #pragma unroll
        for (int q = 0; q < 4; q++) {
            float2 f = __half22float2(u2h2(eu[q]));
            float px = __expf(f.x), py = __expf(f.y);
            s += px + py;
            p[q] = __floats2half2_rn(px, py);
        }
        #pragma unroll
        for (int c = 0; c < Cc; c++) {
            uint4 xv = ((const uint4*)(xh2s + c * 128))[jh * 16 + li];
            v2[c] = __hfma2(p[0], u2h2(xv.x), v2[c]);
            v2[c] = __hfma2(p[1], u2h2(xv.y), v2[c]);
            v2[c] = __hfma2(p[2], u2h2(xv.z), v2[c]);
            v2[c] = __hfma2(p[3], u2h2(xv.w), v2[c]);
        }
    }

    // reduce within 16-lane groups (rows stay separate)
    #pragma unroll
    for (int off = 8; off; off >>= 1)
        s += __shfl_xor_sync(0xffffffffu, s, off);

    float my0 = 0.f, my1 = 0.f;
    #pragma unroll
    for (int c = 0; c < Cc; c++) {
        float2 f = __half22float2(v2[c]);
        float tc = f.x + f.y;
        #pragma unroll
        for (int off = 8; off; off >>= 1)
            tc += __shfl_xor_sync(0xffffffffu, tc, off);
        if (c < 16) { if (li == c)      my0 = tc; }
        else        { if (li == c - 16) my1 = tc; }
    }

    // ---- cross-jh merge (ordered write/add) ----
    if (jh == 0) {
        vsh[r * 33 + li]      = my0;
        vsh[r * 33 + li + 16] = my1;
        if (li == 0) ssh[r] = s;
        if (lane == 0) { msh[rA] = mA; msh[rB] = mB; }
    }
    __syncthreads();
    if (jh == 1) {
        vsh[r * 33 + li]      += my0;
        vsh[r * 33 + li + 16] += my1;
        if (li == 0) ssh[r] += s;
        if (lane == 0) {
            msh[rA] = fmaxf(msh[rA], mA);
            msh[rB] = fmaxf(msh[rB], mB);
        }
    }
    __syncthreads();

    // ---- Phase C: warp w writes normalized a for row w ----
    int t = t0 + w;
    size_t row = (size_t)b * Tt + t;
    float inv = 1.f / (ssh[w] + 1e-5f * __expf(msh[w]));
    {
        float* arow = a_out + row * Tt;
        const unsigned* esw = (const unsigned*)es + w * 512;
        #pragma unroll
        for (int q = 0; q < 16; q++) {
            int idx = q * 32 + lane;
            float2 f = __half22float2(u2h2(esw[idx]));
            ((float2*)arow)[idx] = make_float2(__expf(f.x) * inv, __expf(f.y) * inv);
        }
    }
    __syncthreads();   // es/khs dead -> FF weight overlay begins

    for (int i = tid; i < Hh * Cc; i += 256) {
        int h = i >> 5, c = i & 31;
        W1T[c * 129 + h] = W1[i];                 // W1 (H,C) row-major
        int c2 = i >> 7, h2 = i & 127;
        W2p[c2 * 129 + h2] = W2[i];               // W2 (C,H) row-major
    }

    // ---- LN1 (warp w = token w, lane = channel) -> ys ----
    {
        float xres = x[(size_t)b * Cc * Tt + (size_t)lane * Tt + t];
        float z = xres + vsh[w * 33 + lane] * inv;
        float sum = z;
        #pragma unroll
        for (int off = 16; off; off >>= 1)
            sum += __shfl_xor_sync(0xffffffffu, sum, off);
        float mean = sum * (1.f / Cc);
        float d = z - mean;
        float vv = d * d;
        #pragma unroll
        for (int off = 16; off; off >>= 1)
            vv += __shfl_xor_sync(0xffffffffu, vv, off);
        float rstd = rsqrtf(vv * (1.f / Cc) + 1e-14f);
        ys[w * 33 + lane] = d * rstd * g1[lane] + be1[lane];
    }
    __syncthreads();   // weights staged + ys ready

    // ---- FF (warp w = token w) ----
    float acc[4];
    #pragma unroll
    for (int k = 0; k < 4; k++) acc[k] = b1s[lane + 32 * k];
    #pragma unroll
    for (int c = 0; c < Cc; c++) {
        float yv = ys[w * 33 + c];
        #pragma unroll
        for (int k = 0; k < 4; k++)
            acc[k] += yv * W1T[c * 129 + lane + 32 * k];
    }
    #pragma unroll
    for (int k = 0; k < 4; k++)
        h1s[w * 132 + lane + 32 * k] = fmaxf(acc[k], 0.f);
    __syncwarp();

    float a2 = 0.f;
    #pragma unroll 4
    for (int h = 0; h < Hh; h++)
        a2 += h1s[w * 132 + h] * W2p[lane * 129 + h];

    {
        float z = ys[w * 33 + lane] + a2 + b2s[lane];
        float sum = z;
        #pragma unroll
        for (int off = 16; off; off >>= 1)
            sum += __shfl_xor_sync(0xffffffffu, sum, off);
        float mean = sum * (1.f / Cc);
        float d = z - mean;
        float vv = d * d;
        #pragma unroll
        for (int off = 16; off; off >>= 1)
            vv += __shfl_xor_sync(0xffffffffu, vv, off);
        float rstd = rsqrtf(vv * (1.f / Cc) + 1e-14f);
        y2[(size_t)b * Cc * Tt + (size_t)lane * Tt + t] = d * rstd * g2s[lane] + be2s[lane];
    }
}

// ---------------------------------------------------------------------------
extern "C" void kernel_launch(void* const* d_in, const int* in_sizes, int n_in,
                              void* d_out, int out_size) {
    (void)in_sizes; (void)n_in; (void)out_size;
    const float* x   = (const float*)d_in[0];
    const float* Wt  = (const float*)d_in[1];
    const float* Wx  = (const float*)d_in[2];
    const float* bh  = (const float*)d_in[3];
    const float* Wa  = (const float*)d_in[4];
    const float* ba  = (const float*)d_in[5];
    const float* g1  = (const float*)d_in[6];
    const float* be1 = (const float*)d_in[7];
    const float* W1  = (const float*)d_in[8];
    const float* b1  = (const float*)d_in[9];
    const float* W2  = (const float*)d_in[10];
    const float* b2  = (const float*)d_in[11];
    const float* g2  = (const float*)d_in[12];
    const float* be2 = (const float*)d_in[13];

    float* out = (float*)d_out;
    float* y2  = out;                    // (B,C,T) = 131072 floats
    float* a   = out + Bq * Cc * Tt;     // (B,T,T) = 4194304 floats

    cudaFuncSetAttribute(k_fused, cudaFuncAttributeMaxDynamicSharedMemorySize, SMEM_FUSED);

    k_prep <<<Bq * (Tt / 8), 256>>>(x, Wt, Wx, bh);
    k_fused<<<Bq * (Tt / 8), 256, SMEM_FUSED>>>(x, a, Wa, ba, g1, be1,
                                                W1, b1, W2, b2, g2, be2, y2);
}

// round 13
// speedup vs baseline: 1.0354x; 1.0354x over previous
#include <cuda_runtime.h>
#include <cuda_fp16.h>
#include <cuda_pipeline.h>

#define Bq 4
#define Cc 32
#define Tt 1024
#define Uu 32
#define Hh 128
#define NCHK 4                  // 256-j chunks

// Scratch — device globals (no allocations allowed).
__device__ float    g_qp[Bq * Tt * Uu];            // q + bh, (B,T,U) f32
__device__ unsigned g_kh_u[Bq * Uu * Tt / 2];      // k as f16, (B,U,T)
__device__ unsigned g_xh_u[Bq * Cc * Tt / 2];      // x as f16, (B,C,T)

__device__ __forceinline__ __half2 tanh2(__half2 x) {
    unsigned xi = *reinterpret_cast<unsigned*>(&x), ri;
    asm("tanh.approx.f16x2 %0, %1;" : "=r"(ri) : "r"(xi));
    return *reinterpret_cast<__half2*>(&ri);
}
__device__ __forceinline__ __half2 u2h2(unsigned u) { return *reinterpret_cast<__half2*>(&u); }
__device__ __forceinline__ unsigned h22u(__half2 h) { return *reinterpret_cast<unsigned*>(&h); }

// ---------------------------------------------------------------------------
// k_prep (R8, proven): 8 tokens/block, grid = B*(T/8) = 512, 256 threads.
// ---------------------------------------------------------------------------
__global__ void __launch_bounds__(256) k_prep(const float* __restrict__ x,
                                              const float* __restrict__ Wt,
                                              const float* __restrict__ Wx,
                                              const float* __restrict__ bh) {
    __shared__ float xs[Cc][9];
    __shared__ float Wts[Cc][33];
    __shared__ float Wxs[Cc][33];
    __shared__ float bhs[Uu];
    __shared__ __half kts[Uu][10];

    int b  = blockIdx.x >> 7;
    int t0 = (blockIdx.x & 127) * 8;
    int tid = threadIdx.x, w = tid >> 5, lane = tid & 31;

    {
        int c = tid >> 3, tl = tid & 7;
        xs[c][tl] = x[(size_t)b * Cc * Tt + (size_t)c * Tt + t0 + tl];
    }
    for (int i = tid; i < Cc * Uu; i += 256) {
        int c = i >> 5, u = i & 31;
        Wts[c][u] = Wt[i];
        Wxs[c][u] = Wx[i];
    }
    if (tid < Uu) bhs[tid] = bh[tid];
    __syncthreads();

    {
        int tl = w, u = lane;
        float accq = bhs[u], acck = 0.f;
        #pragma unroll
        for (int c = 0; c < Cc; c++) {
            float xv = xs[c][tl];
            accq += xv * Wts[c][u];
            acck += xv * Wxs[c][u];
        }
        g_qp[((size_t)b * Tt + t0 + tl) * Uu + u] = accq;
        kts[u][tl] = __float2half(acck);
    }
    __syncthreads();

    if (tid < 128) {
        int r = tid >> 2, g = tid & 3;
        __half* kh = (__half*)g_kh_u;
        __half2 kv = __halves2half2(kts[r][2 * g], kts[r][2 * g + 1]);
        *(unsigned*)(kh + ((size_t)b * Uu + r) * Tt + t0 + 2 * g) = h22u(kv);
        __half* xh = (__half*)g_xh_u;
        __half2 xv = __floats2half2_rn(xs[r][2 * g], xs[r][2 * g + 1]);
        *(unsigned*)(xh + ((size_t)b * Cc + r) * Tt + t0 + 2 * g) = h22u(xv);
    }
}

// ---------------------------------------------------------------------------
// k_fused v4: R10 shape (128 thr, 4 warps, 2 rows/warp, grid B*(T/8)=512)
// + cp.async double-buffered tiles + 8 accumulator chains.
// ---------------------------------------------------------------------------
#define OFF_K0   0                           // half2 buf0[32][128] 16384 | W1T overlay
#define OFF_K1   16384                       // half2 buf1[32][128] 16384 | W2p overlay
#define OFF_E    32768                       // half2 es[8][512]    16384
#define OFF_WA   49152                       // half2 was[32]         128
#define OFF_Q    49280                       // float qsm[8*33]      1056
#define OFF_YS   50336                       // float ys[8*33]       1056
#define OFF_H1   51392                       // float h1s[8*132]     4224
#define OFF_B1   55616                       // float b1s[128]        512
#define OFF_B2   56128                       // float b2s[32]         128
#define OFF_G2   56256                       // float g2s[32]         128
#define OFF_BE2  56384                       // float be2s[32]        128
#define SMEM_FUSED 56512

__global__ void __launch_bounds__(128) k_fused(const float* __restrict__ x,
                                               float* __restrict__ a_out,
                                               const float* __restrict__ Wa,
                                               const float* __restrict__ ba,
                                               const float* __restrict__ g1,
                                               const float* __restrict__ be1,
                                               const float* __restrict__ W1,
                                               const float* __restrict__ b1,
                                               const float* __restrict__ W2,
                                               const float* __restrict__ b2,
                                               const float* __restrict__ g2,
                                               const float* __restrict__ be2,
                                               float* __restrict__ y2) {
    extern __shared__ char dyn[];
    __half2* kbuf[2] = { (__half2*)(dyn + OFF_K0), (__half2*)(dyn + OFF_K1) };
    __half2* es   = (__half2*)(dyn + OFF_E);    // [8][512]
    __half2* was  = (__half2*)(dyn + OFF_WA);
    float* qsm  = (float*)(dyn + OFF_Q);
    float* W1T  = (float*)(dyn + OFF_K0);       // FF overlay (bufs dead)
    float* W2p  = (float*)(dyn + OFF_K0 + 16512);
    float* ys   = (float*)(dyn + OFF_YS);
    float* h1s  = (float*)(dyn + OFF_H1);
    float* b1s  = (float*)(dyn + OFF_B1);
    float* b2s  = (float*)(dyn + OFF_B2);
    float* g2s  = (float*)(dyn + OFF_G2);
    float* be2s = (float*)(dyn + OFF_BE2);

    int b  = blockIdx.x >> 7;
    int t0 = (blockIdx.x & 127) * 8;
    int tid = threadIdx.x, w = tid >> 5, lane = tid & 31;
    int rA = 2 * w, rB = rA + 1;
    int tA = t0 + rA, tB = t0 + rB;
    size_t rowA = (size_t)b * Tt + tA, rowB = (size_t)b * Tt + tB;

    const uint4* kb4 = (const uint4*)g_kh_u + (size_t)b * (Uu * Tt / 8);
    const uint4* xsrc = (const uint4*)g_xh_u + (size_t)b * (Cc * Tt / 8);

    // async prefetch of k chunk 0 into buf0 (8 uint4/thread)
    #pragma unroll
    for (int k = 0; k < 8; k++) {
        int idx = tid + k * 128;
        int r = idx >> 5, g = idx & 31;
        __pipeline_memcpy_async((uint4*)kbuf[0] + idx, kb4 + r * 128 + g, 16);
    }
    __pipeline_commit();

    // ---- staging (overlaps with async copy) ----
    for (int i = tid; i < 8 * Uu; i += 128) {
        int r = i >> 5, u = i & 31;
        qsm[r * 33 + u] = g_qp[((size_t)b * Tt + t0 + r) * Uu + u];
    }
    if (tid < Uu) was[tid] = __float2half2_rn(Wa[tid]);
    if (tid < Hh) b1s[tid] = b1[tid];
    if (tid < Cc) { b2s[tid] = b2[tid]; g2s[tid] = g2[tid]; be2s[tid] = be2[tid]; }
    __syncthreads();

    __half2 qA[Uu], qB[Uu];
    #pragma unroll
    for (int u = 0; u < Uu; u++) {
        qA[u] = __float2half2_rn(qsm[rA * 33 + u]);
        qB[u] = __float2half2_rn(qsm[rB * 33 + u]);
    }
    __half2 ba2  = __float2half2_rn(ba[0]);
    __half2 mA2  = __float2half2_rn(-60000.f), mB2 = mA2;
    __half2 z2   = __float2half2_rn(0.f);
    __half2 one2 = __float2half2_rn(1.f);
    __half2 ca2  = __float2half2_rn(-1.f / 3.f);
    __half2 cb2  = __float2half2_rn(2.f / 15.f);

    // ---- Phase A: e in smem, double-buffered k tiles ----
    for (int ch = 0; ch < NCHK; ch++) {
        __pipeline_wait_prior(0);
        __syncthreads();                       // current buf visible to all
        if (ch < NCHK - 1) {                   // prefetch next chunk
            #pragma unroll
            for (int k = 0; k < 8; k++) {
                int idx = tid + k * 128;
                int r = idx >> 5, g = idx & 31;
                __pipeline_memcpy_async((uint4*)kbuf[(ch + 1) & 1] + idx,
                                        kb4 + r * 128 + (ch + 1) * 32 + g, 16);
            }
            __pipeline_commit();
        }
        const __half2* khs = kbuf[ch & 1];

        #pragma unroll
        for (int jt = 0; jt < 4; jt++) {
            int pj = jt * 32 + lane;
            __half2 aE0 = z2, aE1 = z2, aO0 = z2, aO1 = z2;
            __half2 bE0 = z2, bE1 = z2, bO0 = z2, bO1 = z2;
            #pragma unroll
            for (int u = 0; u < Uu; u += 4) {
                __half2 k0 = khs[u * 128 + pj];
                __half2 k1 = khs[(u + 1) * 128 + pj];
                __half2 k2 = khs[(u + 2) * 128 + pj];
                __half2 k3 = khs[(u + 3) * 128 + pj];
                // even u, u+2: MUFU
                aE0 = __hfma2(was[u],     tanh2(__hadd2(qA[u],     k0)), aE0);
                bE0 = __hfma2(was[u],     tanh2(__hadd2(qB[u],     k0)), bE0);
                aE1 = __hfma2(was[u + 2], tanh2(__hadd2(qA[u + 2], k2)), aE1);
                bE1 = __hfma2(was[u + 2], tanh2(__hadd2(qB[u + 2], k2)), bE1);
                // odd u+1, u+3: poly
                {
                    __half2 xp = __hadd2(qA[u + 1], k1);
                    __half2 x2 = __hmul2(xp, xp);
                    __half2 tp = __hfma2(x2, cb2, ca2); tp = __hfma2(x2, tp, one2);
                    aO0 = __hfma2(was[u + 1], __hmul2(xp, tp), aO0);
                }
                {
                    __half2 xp = __hadd2(qB[u + 1], k1);
                    __half2 x2 = __hmul2(xp, xp);
                    __half2 tp = __hfma2(x2, cb2, ca2); tp = __hfma2(x2, tp, one2);
                    bO0 = __hfma2(was[u + 1], __hmul2(xp, tp), bO0);
                }
                {
                    __half2 xp = __hadd2(qA[u + 3], k3);
                    __half2 x2 = __hmul2(xp, xp);
                    __half2 tp = __hfma2(x2, cb2, ca2); tp = __hfma2(x2, tp, one2);
                    aO1 = __hfma2(was[u + 3], __hmul2(xp, tp), aO1);
                }
                {
                    __half2 xp = __hadd2(qB[u + 3], k3);
                    __half2 x2 = __hmul2(xp, xp);
                    __half2 tp = __hfma2(x2, cb2, ca2); tp = __hfma2(x2, tp, one2);
                    bO1 = __hfma2(was[u + 3], __hmul2(xp, tp), bO1);
                }
            }
            __half2 eA2 = __hadd2(__hadd2(__hadd2(aE0, aE1), __hadd2(aO0, aO1)), ba2);
            __half2 eB2 = __hadd2(__hadd2(__hadd2(bE0, bE1), __hadd2(bO0, bO1)), ba2);
            mA2 = __hmax2(mA2, eA2);
            mB2 = __hmax2(mB2, eB2);
            es[rA * 512 + ch * 128 + pj] = eA2;
            es[rB * 512 + ch * 128 + pj] = eB2;
        }
    }

    // prefetch x chunk 0 into buf0 (Phase A's last compute used buf1)
    #pragma unroll
    for (int k = 0; k < 8; k++) {
        int idx = tid + k * 128;
        int r = idx >> 5, g = idx & 31;
        __pipeline_memcpy_async((uint4*)kbuf[0] + idx, xsrc + r * 128 + g, 16);
    }
    __pipeline_commit();

    float mA = fmaxf(__low2float(mA2), __high2float(mA2));
    float mB = fmaxf(__low2float(mB2), __high2float(mB2));
    #pragma unroll
    for (int off = 16; off; off >>= 1) {
        mA = fmaxf(mA, __shfl_xor_sync(0xffffffffu, mA, off));
        mB = fmaxf(mB, __shfl_xor_sync(0xffffffffu, mB, off));
    }

    // ---- Phase B: s + unnormalized v, double-buffered x tiles ----
    float sA = 0.f, sB = 0.f;
    __half2 vA[Cc], vB[Cc];
    #pragma unroll
    for (int c = 0; c < Cc; c++) { vA[c] = z2; vB[c] = z2; }

    for (int ch = 0; ch < NCHK; ch++) {
        __pipeline_wait_prior(0);
        __syncthreads();
        if (ch < NCHK - 1) {
            #pragma unroll
            for (int k = 0; k < 8; k++) {
                int idx = tid + k * 128;
                int r = idx >> 5, g = idx & 31;
                __pipeline_memcpy_async((uint4*)kbuf[(ch + 1) & 1] + idx,
                                        xsrc + r * 128 + (ch + 1) * 32 + g, 16);
            }
            __pipeline_commit();
        }
        const __half2* xh2s = kbuf[ch & 1];

        #pragma unroll
        for (int q = 0; q < 2; q++) {
            int g   = ch * 32 + q * 16 + (lane & 15);
            int lp4 = q * 16 + (lane & 15);
            // lanes split rows: 0-15 -> A-half? No: keep R10 mapping, 32 lanes sweep 32 uint4
            (void)g; (void)lp4;
        }
        // R10 mapping: lane sweeps 32 uint4 of the 128-pair chunk, q in {0,1} -> 2x32
        #pragma unroll
        for (int q = 0; q < 1; q++) { }
        {
            // each chunk has 32 uint4 per row (128 pairs); lane = one uint4
            uint4 ea = ((const uint4*)(es + rA * 512))[ch * 32 + lane];
            uint4 eb = ((const uint4*)(es + rB * 512))[ch * 32 + lane];
            unsigned eua[4] = {ea.x, ea.y, ea.z, ea.w};
            unsigned eub[4] = {eb.x, eb.y, eb.z, eb.w};
            __half2 pA[4], pB[4];
            #pragma unroll
            for (int r = 0; r < 4; r++) {
                float2 fa = __half22float2(u2h2(eua[r]));
                float2 fb = __half22float2(u2h2(eub[r]));
                float pax = __expf(fa.x), pay = __expf(fa.y);
                float pbx = __expf(fb.x), pby = __expf(fb.y);
                sA += pax + pay; sB += pbx + pby;
                pA[r] = __floats2half2_rn(pax, pay);
                pB[r] = __floats2half2_rn(pbx, pby);
            }
            #pragma unroll
            for (int c = 0; c < Cc; c++) {
                uint4 xv = ((const uint4*)(xh2s + c * 128))[lane];
                vA[c] = __hfma2(pA[0], u2h2(xv.x), vA[c]);
                vA[c] = __hfma2(pA[1], u2h2(xv.y), vA[c]);
                vA[c] = __hfma2(pA[2], u2h2(xv.z), vA[c]);
                vA[c] = __hfma2(pA[3], u2h2(xv.w), vA[c]);
                vB[c] = __hfma2(pB[0], u2h2(xv.x), vB[c]);
                vB[c] = __hfma2(pB[1], u2h2(xv.y), vB[c]);
                vB[c] = __hfma2(pB[2], u2h2(xv.z), vB[c]);
                vB[c] = __hfma2(pB[3], u2h2(xv.w), vB[c]);
            }
        }
    }

    float vfA[Cc], vfB[Cc];
    #pragma unroll
    for (int c = 0; c < Cc; c++) {
        float2 fa = __half22float2(vA[c]); vfA[c] = fa.x + fa.y;
        float2 fb = __half22float2(vB[c]); vfB[c] = fb.x + fb.y;
    }
    #pragma unroll
    for (int off = 16; off; off >>= 1) {
        sA += __shfl_xor_sync(0xffffffffu, sA, off);
        sB += __shfl_xor_sync(0xffffffffu, sB, off);
    }
    float invA = 1.f / (sA + 1e-5f * __expf(mA));
    float invB = 1.f / (sB + 1e-5f * __expf(mB));

    // ---- Phase C: normalized a from smem e ----
    {
        float* arowA = a_out + rowA * Tt;
        float* arowB = a_out + rowB * Tt;
        const unsigned* esA = (const unsigned*)(es + rA * 512);
        const unsigned* esB = (const unsigned*)(es + rB * 512);
        #pragma unroll
        for (int q = 0; q < 16; q++) {
            int idx = q * 32 + lane;
            float2 fa = __half22float2(u2h2(esA[idx]));
            float2 fb = __half22float2(u2h2(esB[idx]));
            ((float2*)arowA)[idx] = make_float2(__expf(fa.x) * invA, __expf(fa.y) * invA);
            ((float2*)arowB)[idx] = make_float2(__expf(fb.x) * invB, __expf(fb.y) * invB);
        }
    }

    float mineA = 0.f, mineB = 0.f;
    #pragma unroll
    for (int c = 0; c < Cc; c++) {
        float ta = vfA[c], tb = vfB[c];
        #pragma unroll
        for (int off = 16; off; off >>= 1) {
            ta += __shfl_xor_sync(0xffffffffu, ta, off);
            tb += __shfl_xor_sync(0xffffffffu, tb, off);
        }
        if (lane == c) { mineA = ta; mineB = tb; }
    }

    __syncthreads();   // bufs + es dead -> FF weight overlay

    for (int i = tid; i < Hh * Cc; i += 128) {
        int h = i >> 5, c = i & 31;
        W1T[c * 129 + h] = W1[i];
        int c2 = i >> 7, h2 = i & 127;
        W2p[c2 * 129 + h2] = W2[i];
    }

    // ---- LN1 (lane = channel) -> ys ----
    const float* xb = x + (size_t)b * Cc * Tt + (size_t)lane * Tt;
    #pragma unroll
    for (int r = 0; r < 2; r++) {
        int t = (r == 0) ? tA : tB;
        float z = xb[t] + ((r == 0) ? mineA * invA : mineB * invB);
        float sum = z;
        #pragma unroll
        for (int off = 16; off; off >>= 1)
            sum += __shfl_xor_sync(0xffffffffu, sum, off);
        float mean = sum * (1.f / Cc);
        float d = z - mean;
        float vv = d * d;
        #pragma unroll
        for (int off = 16; off; off >>= 1)
            vv += __shfl_xor_sync(0xffffffffu, vv, off);
        float rstd = rsqrtf(vv * (1.f / Cc) + 1e-14f);
        ys[(2 * w + r) * 33 + lane] = d * rstd * g1[lane] + be1[lane];
    }
    __syncthreads();   // weights staged + ys ready

    // ---- FF (intra-warp, tokens 2w, 2w+1) ----
    int tokbase = 2 * w;
    float acc[4][2];
    #pragma unroll
    for (int k = 0; k < 4; k++) {
        float bb = b1s[lane + 32 * k];
        acc[k][0] = bb; acc[k][1] = bb;
    }
    #pragma unroll
    for (int c = 0; c < Cc; c++) {
        float yv0 = ys[tokbase * 33 + c];
        float yv1 = ys[(tokbase + 1) * 33 + c];
        #pragma unroll
        for (int k = 0; k < 4; k++) {
            float wv = W1T[c * 129 + lane + 32 * k];
            acc[k][0] += yv0 * wv;
            acc[k][1] += yv1 * wv;
        }
    }
    #pragma unroll
    for (int k = 0; k < 4; k++) {
        h1s[tokbase * 132 + lane + 32 * k]       = fmaxf(acc[k][0], 0.f);
        h1s[(tokbase + 1) * 132 + lane + 32 * k] = fmaxf(acc[k][1], 0.f);
    }
    __syncwarp();

    float a2[2] = {0.f, 0.f};
    #pragma unroll 4
    for (int h = 0; h < Hh; h++) {
        float wv = W2p[lane * 129 + h];
        a2[0] += h1s[tokbase * 132 + h] * wv;
        a2[1] += h1s[(tokbase + 1) * 132 + h] * wv;
    }

    #pragma unroll
    for (int tk = 0; tk < 2; tk++) {
        int tok = tokbase + tk;
        int t = t0 + tok;
        float z = ys[tok * 33 + lane] + a2[tk] + b2s[lane];
        float sum = z;
        #pragma unroll
        for (int off = 16; off; off >>= 1)
            sum += __shfl_xor_sync(0xffffffffu, sum, off);
        float mean = sum * (1.f / Cc);
        float d = z - mean;
        float vv = d * d;
        #pragma unroll
        for (int off = 16; off; off >>= 1)
            vv += __shfl_xor_sync(0xffffffffu, vv, off);
        float rstd = rsqrtf(vv * (1.f / Cc) + 1e-14f);
        y2[(size_t)b * Cc * Tt + (size_t)lane * Tt + t] = d * rstd * g2s[lane] + be2s[lane];
    }
}

// ---------------------------------------------------------------------------
extern "C" void kernel_launch(void* const* d_in, const int* in_sizes, int n_in,
                              void* d_out, int out_size) {
    (void)in_sizes; (void)n_in; (void)out_size;
    const float* x   = (const float*)d_in[0];
    const float* Wt  = (const float*)d_in[1];
    const float* Wx  = (const float*)d_in[2];
    const float* bh  = (const float*)d_in[3];
    const float* Wa  = (const float*)d_in[4];
    const float* ba  = (const float*)d_in[5];
    const float* g1  = (const float*)d_in[6];
    const float* be1 = (const float*)d_in[7];
    const float* W1  = (const float*)d_in[8];
    const float* b1  = (const float*)d_in[9];
    const float* W2  = (const float*)d_in[10];
    const float* b2  = (const float*)d_in[11];
    const float* g2  = (const float*)d_in[12];
    const float* be2 = (const float*)d_in[13];

    float* out = (float*)d_out;
    float* y2  = out;                    // (B,C,T) = 131072 floats
    float* a   = out + Bq * Cc * Tt;     // (B,T,T) = 4194304 floats

    cudaFuncSetAttribute(k_fused, cudaFuncAttributeMaxDynamicSharedMemorySize, SMEM_FUSED);

    k_prep <<<Bq * (Tt / 8), 256>>>(x, Wt, Wx, bh);
    k_fused<<<Bq * (Tt / 8), 128, SMEM_FUSED>>>(x, a, Wa, ba, g1, be1,
                                                W1, b1, W2, b2, g2, be2, y2);
}

// round 14
// speedup vs baseline: 1.2001x; 1.1591x over previous
#include <cuda_runtime.h>
#include <cuda_fp16.h>

#define Bq 4
#define Cc 32
#define Tt 1024
#define Uu 32
#define Hh 128
#define NCHK 4                  // 256-j chunks

// Scratch — device globals (no allocations allowed).
__device__ float    g_qp[Bq * Tt * Uu];            // q + bh, (B,T,U) f32
__device__ unsigned g_kh_u[Bq * Uu * Tt / 2];      // k as f16, (B,U,T)
__device__ unsigned g_xh_u[Bq * Cc * Tt / 2];      // x as f16, (B,C,T)

__device__ __forceinline__ __half2 tanh2(__half2 x) {
    unsigned xi = *reinterpret_cast<unsigned*>(&x), ri;
    asm("tanh.approx.f16x2 %0, %1;" : "=r"(ri) : "r"(xi));
    return *reinterpret_cast<__half2*>(&ri);
}
__device__ __forceinline__ __half2 u2h2(unsigned u) { return *reinterpret_cast<__half2*>(&u); }
__device__ __forceinline__ unsigned h22u(__half2 h) { return *reinterpret_cast<unsigned*>(&h); }

// ---------------------------------------------------------------------------
// k_prep (R8, proven): 8 tokens/block, grid = B*(T/8) = 512, 256 threads.
// ---------------------------------------------------------------------------
__global__ void __launch_bounds__(256) k_prep(const float* __restrict__ x,
                                              const float* __restrict__ Wt,
                                              const float* __restrict__ Wx,
                                              const float* __restrict__ bh) {
    __shared__ float xs[Cc][9];
    __shared__ float Wts[Cc][33];
    __shared__ float Wxs[Cc][33];
    __shared__ float bhs[Uu];
    __shared__ __half kts[Uu][10];

    int b  = blockIdx.x >> 7;
    int t0 = (blockIdx.x & 127) * 8;
    int tid = threadIdx.x, w = tid >> 5, lane = tid & 31;

    {
        int c = tid >> 3, tl = tid & 7;
        xs[c][tl] = x[(size_t)b * Cc * Tt + (size_t)c * Tt + t0 + tl];
    }
    for (int i = tid; i < Cc * Uu; i += 256) {
        int c = i >> 5, u = i & 31;
        Wts[c][u] = Wt[i];
        Wxs[c][u] = Wx[i];
    }
    if (tid < Uu) bhs[tid] = bh[tid];
    __syncthreads();

    {
        int tl = w, u = lane;
        float accq = bhs[u], acck = 0.f;
        #pragma unroll
        for (int c = 0; c < Cc; c++) {
            float xv = xs[c][tl];
            accq += xv * Wts[c][u];
            acck += xv * Wxs[c][u];
        }
        g_qp[((size_t)b * Tt + t0 + tl) * Uu + u] = accq;
        kts[u][tl] = __float2half(acck);
    }
    __syncthreads();

    if (tid < 128) {
        int r = tid >> 2, g = tid & 3;
        __half* kh = (__half*)g_kh_u;
        __half2 kv = __halves2half2(kts[r][2 * g], kts[r][2 * g + 1]);
        *(unsigned*)(kh + ((size_t)b * Uu + r) * Tt + t0 + 2 * g) = h22u(kv);
        __half* xh = (__half*)g_xh_u;
        __half2 xv = __floats2half2_rn(xs[r][2 * g], xs[r][2 * g + 1]);
        *(unsigned*)(xh + ((size_t)b * Cc + r) * Tt + t0 + 2 * g) = h22u(xv);
    }
}

// ---------------------------------------------------------------------------
// k_fused (R10 shape): 8 rows/block, 128 threads, warp w owns rows 2w, 2w+1.
// grid = B*(T/8) = 512. Deg-3 poly, 14/18 MUFU/poly split; p stored into es.
// ---------------------------------------------------------------------------
#define OFF_K    0                           // half2 khs[32][128] 16384 | x-tile | W1T overlay
#define OFF_E    16384                       // half2 es[8][512]   16384 | W2p overlay
#define OFF_WA   32768                       // half2 was[32]        128 (dead by FF)
#define OFF_Q    32896                       // float qsm[8*33]     1056 (dead by FF)
#define OFF_YS   33952                       // float ys[8*33]      1056
#define OFF_H1   35008                       // float h1s[8*132]    4224
#define OFF_B1   39232                       // float b1s[128]       512
#define OFF_B2   39744                       // float b2s[32]        128
#define OFF_G2   39872                       // float g2s[32]        128
#define OFF_BE2  40000                       // float be2s[32]       128
#define SMEM_FUSED 40128

// deg-3 poly tanh on FMA pipe: t = x*(1 - x^2/3)
#define POLY3(dst, q, k, wa)                                        \
    {                                                               \
        __half2 xp = __hadd2((q), (k));                             \
        __half2 x2 = __hmul2(xp, xp);                               \
        __half2 tp = __hfma2(x2, ca2, one2);                        \
        (dst) = __hfma2((wa), __hmul2(xp, tp), (dst));              \
    }

__global__ void __launch_bounds__(128) k_fused(const float* __restrict__ x,
                                               float* __restrict__ a_out,
                                               const float* __restrict__ Wa,
                                               const float* __restrict__ ba,
                                               const float* __restrict__ g1,
                                               const float* __restrict__ be1,
                                               const float* __restrict__ W1,
                                               const float* __restrict__ b1,
                                               const float* __restrict__ W2,
                                               const float* __restrict__ b2,
                                               const float* __restrict__ g2,
                                               const float* __restrict__ be2,
                                               float* __restrict__ y2) {
    extern __shared__ char dyn[];
    __half2* khs  = (__half2*)(dyn + OFF_K);    // [32][128]
    __half2* es   = (__half2*)(dyn + OFF_E);    // [8][512]: e in Phase A, p after B
    __half2* was  = (__half2*)(dyn + OFF_WA);
    float* qsm  = (float*)(dyn + OFF_Q);
    float* W1T  = (float*)(dyn + OFF_K);        // FF overlay
    float* W2p  = (float*)(dyn + OFF_K + 16512);
    float* ys   = (float*)(dyn + OFF_YS);
    float* h1s  = (float*)(dyn + OFF_H1);
    float* b1s  = (float*)(dyn + OFF_B1);
    float* b2s  = (float*)(dyn + OFF_B2);
    float* g2s  = (float*)(dyn + OFF_G2);
    float* be2s = (float*)(dyn + OFF_BE2);

    int b  = blockIdx.x >> 7;
    int t0 = (blockIdx.x & 127) * 8;
    int tid = threadIdx.x, w = tid >> 5, lane = tid & 31;
    int rA = 2 * w, rB = rA + 1;
    int tA = t0 + rA, tB = t0 + rB;
    size_t rowA = (size_t)b * Tt + tA, rowB = (size_t)b * Tt + tB;

    // ---- staging ----
    for (int i = tid; i < 8 * Uu; i += 128) {
        int r = i >> 5, u = i & 31;
        qsm[r * 33 + u] = g_qp[((size_t)b * Tt + t0 + r) * Uu + u];
    }
    if (tid < Uu) was[tid] = __float2half2_rn(Wa[tid]);
    if (tid < Hh) b1s[tid] = b1[tid];
    if (tid < Cc) { b2s[tid] = b2[tid]; g2s[tid] = g2[tid]; be2s[tid] = be2[tid]; }
    __syncthreads();

    __half2 qA[Uu], qB[Uu];
    #pragma unroll
    for (int u = 0; u < Uu; u++) {
        qA[u] = __float2half2_rn(qsm[rA * 33 + u]);
        qB[u] = __float2half2_rn(qsm[rB * 33 + u]);
    }
    __half2 ba2  = __float2half2_rn(ba[0]);
    __half2 mA2  = __float2half2_rn(-60000.f), mB2 = mA2;
    __half2 z2   = __float2half2_rn(0.f);
    __half2 one2 = __float2half2_rn(1.f);
    __half2 ca2  = __float2half2_rn(-1.f / 3.f);

    const uint4* kb4 = (const uint4*)g_kh_u + (size_t)b * (Uu * Tt / 8);

    // ---- Phase A: e for rows rA,rB into smem es ----
    for (int ch = 0; ch < NCHK; ch++) {
        __syncthreads();
        #pragma unroll
        for (int k = 0; k < 8; k++) {
            int idx = tid + k * 128;
            int r = idx >> 5, g = idx & 31;
            ((uint4*)khs)[idx] = kb4[r * 128 + ch * 32 + g];
        }
        __syncthreads();

        #pragma unroll
        for (int jt = 0; jt < 4; jt++) {
            int pj = jt * 32 + lane;
            __half2 a0 = z2, a1 = z2, b0 = z2, b1h = z2;
            #pragma unroll
            for (int u = 0; u < Uu; u += 4) {
                __half2 k0 = khs[u * 128 + pj];
                __half2 k1 = khs[(u + 1) * 128 + pj];
                __half2 k2 = khs[(u + 2) * 128 + pj];
                __half2 k3 = khs[(u + 3) * 128 + pj];
                // u+0: MUFU tanh, both rows
                a0 = __hfma2(was[u], tanh2(__hadd2(qA[u], k0)), a0);
                b0 = __hfma2(was[u], tanh2(__hadd2(qB[u], k0)), b0);
                // u+1: poly
                POLY3(a1, qA[u + 1], k1, was[u + 1]);
                POLY3(b1h, qB[u + 1], k1, was[u + 1]);
                // u+2: MUFU for u<24 (14 MUFU total), poly for u>=24
                if (u < 24) {
                    a0 = __hfma2(was[u + 2], tanh2(__hadd2(qA[u + 2], k2)), a0);
                    b0 = __hfma2(was[u + 2], tanh2(__hadd2(qB[u + 2], k2)), b0);
                } else {
                    POLY3(a1, qA[u + 2], k2, was[u + 2]);
                    POLY3(b1h, qB[u + 2], k2, was[u + 2]);
                }
                // u+3: poly
                POLY3(a1, qA[u + 3], k3, was[u + 3]);
                POLY3(b1h, qB[u + 3], k3, was[u + 3]);
            }
            __half2 eA2 = __hadd2(__hadd2(a0, a1), ba2);
            __half2 eB2 = __hadd2(__hadd2(b0, b1h), ba2);
            mA2 = __hmax2(mA2, eA2);
            mB2 = __hmax2(mB2, eB2);
            es[rA * 512 + ch * 128 + pj] = eA2;
            es[rB * 512 + ch * 128 + pj] = eB2;
        }
    }

    float mA = fmaxf(__low2float(mA2), __high2float(mA2));
    float mB = fmaxf(__low2float(mB2), __high2float(mB2));
    #pragma unroll
    for (int off = 16; off; off >>= 1) {
        mA = fmaxf(mA, __shfl_xor_sync(0xffffffffu, mA, off));
        mB = fmaxf(mB, __shfl_xor_sync(0xffffffffu, mB, off));
    }

    // ---- Phase B: s + unnormalized v; p overwrites e in smem ----
    float sA = 0.f, sB = 0.f;
    __half2 vA[Cc], vB[Cc];
    #pragma unroll
    for (int c = 0; c < Cc; c++) { vA[c] = z2; vB[c] = z2; }

    const uint4* xsrc = (const uint4*)g_xh_u + (size_t)b * (Cc * Tt / 8);
    __half2* xh2s = khs;   // overlay

    for (int ch = 0; ch < NCHK; ch++) {
        __syncthreads();
        #pragma unroll
        for (int k = 0; k < 8; k++) {
            int idx = tid + k * 128;
            int r = idx >> 5, g = idx & 31;
            ((uint4*)xh2s)[idx] = xsrc[r * 128 + ch * 32 + g];
        }
        __syncthreads();

        uint4 ea = ((const uint4*)(es + rA * 512))[ch * 32 + lane];
        uint4 eb = ((const uint4*)(es + rB * 512))[ch * 32 + lane];
        unsigned eua[4] = {ea.x, ea.y, ea.z, ea.w};
        unsigned eub[4] = {eb.x, eb.y, eb.z, eb.w};
        __half2 pA[4], pB[4];
        #pragma unroll
        for (int r = 0; r < 4; r++) {
            float2 fa = __half22float2(u2h2(eua[r]));
            float2 fb = __half22float2(u2h2(eub[r]));
            float pax = __expf(fa.x), pay = __expf(fa.y);
            float pbx = __expf(fb.x), pby = __expf(fb.y);
            sA += pax + pay; sB += pbx + pby;
            pA[r] = __floats2half2_rn(pax, pay);
            pB[r] = __floats2half2_rn(pbx, pby);
        }
        // overwrite e with p (lane-private slots; p in [exp(-0.7), exp(0.7)])
        {
            uint4 pu_a = make_uint4(h22u(pA[0]), h22u(pA[1]), h22u(pA[2]), h22u(pA[3]));
            uint4 pu_b = make_uint4(h22u(pB[0]), h22u(pB[1]), h22u(pB[2]), h22u(pB[3]));
            ((uint4*)(es + rA * 512))[ch * 32 + lane] = pu_a;
            ((uint4*)(es + rB * 512))[ch * 32 + lane] = pu_b;
        }
        #pragma unroll
        for (int c = 0; c < Cc; c++) {
            uint4 xv = ((const uint4*)(xh2s + c * 128))[lane];
            vA[c] = __hfma2(pA[0], u2h2(xv.x), vA[c]);
            vA[c] = __hfma2(pA[1], u2h2(xv.y), vA[c]);
            vA[c] = __hfma2(pA[2], u2h2(xv.z), vA[c]);
            vA[c] = __hfma2(pA[3], u2h2(xv.w), vA[c]);
            vB[c] = __hfma2(pB[0], u2h2(xv.x), vB[c]);
            vB[c] = __hfma2(pB[1], u2h2(xv.y), vB[c]);
            vB[c] = __hfma2(pB[2], u2h2(xv.z), vB[c]);
            vB[c] = __hfma2(pB[3], u2h2(xv.w), vB[c]);
        }
    }

    float vfA[Cc], vfB[Cc];
    #pragma unroll
    for (int c = 0; c < Cc; c++) {
        float2 fa = __half22float2(vA[c]); vfA[c] = fa.x + fa.y;
        float2 fb = __half22float2(vB[c]); vfB[c] = fb.x + fb.y;
    }

    #pragma unroll
    for (int off = 16; off; off >>= 1) {
        sA += __shfl_xor_sync(0xffffffffu, sA, off);
        sB += __shfl_xor_sync(0xffffffffu, sB, off);
    }
    float invA = 1.f / (sA + 1e-5f * __expf(mA));
    float invB = 1.f / (sB + 1e-5f * __expf(mB));

    // ---- Phase C: a = p * inv straight from smem (no exp recompute) ----
    {
        float* arowA = a_out + rowA * Tt;
        float* arowB = a_out + rowB * Tt;
        const unsigned* esA = (const unsigned*)(es + rA * 512);
        const unsigned* esB = (const unsigned*)(es + rB * 512);
        #pragma unroll
        for (int q = 0; q < 16; q++) {
            int idx = q * 32 + lane;
            float2 fa = __half22float2(u2h2(esA[idx]));
            float2 fb = __half22float2(u2h2(esB[idx]));
            ((float2*)arowA)[idx] = make_float2(fa.x * invA, fa.y * invA);
            ((float2*)arowB)[idx] = make_float2(fb.x * invB, fb.y * invB);
        }
    }

    float mineA = 0.f, mineB = 0.f;
    #pragma unroll
    for (int c = 0; c < Cc; c++) {
        float ta = vfA[c], tb = vfB[c];
        #pragma unroll
        for (int off = 16; off; off >>= 1) {
            ta += __shfl_xor_sync(0xffffffffu, ta, off);
            tb += __shfl_xor_sync(0xffffffffu, tb, off);
        }
        if (lane == c) { mineA = ta; mineB = tb; }
    }

    __syncthreads();   // es/khs dead -> FF weight overlay begins

    for (int i = tid; i < Hh * Cc; i += 128) {
        int h = i >> 5, c = i & 31;
        W1T[c * 129 + h] = W1[i];                 // W1 (H,C) row-major
        int c2 = i >> 7, h2 = i & 127;
        W2p[c2 * 129 + h2] = W2[i];               // W2 (C,H) row-major
    }

    // ---- LN1 (lane = channel) -> ys ----
    const float* xb = x + (size_t)b * Cc * Tt + (size_t)lane * Tt;
    #pragma unroll
    for (int r = 0; r < 2; r++) {
        int t = (r == 0) ? tA : tB;
        float z = xb[t] + ((r == 0) ? mineA * invA : mineB * invB);
        float sum = z;
        #pragma unroll
        for (int off = 16; off; off >>= 1)
            sum += __shfl_xor_sync(0xffffffffu, sum, off);
        float mean = sum * (1.f / Cc);
        float d = z - mean;
        float vv = d * d;
        #pragma unroll
        for (int off = 16; off; off >>= 1)
            vv += __shfl_xor_sync(0xffffffffu, vv, off);
        float rstd = rsqrtf(vv * (1.f / Cc) + 1e-14f);
        ys[(2 * w + r) * 33 + lane] = d * rstd * g1[lane] + be1[lane];
    }
    __syncthreads();   // weights staged + ys ready

    // ---- FF (intra-warp, tokens 2w, 2w+1) ----
    int tokbase = 2 * w;
    float acc[4][2];
    #pragma unroll
    for (int k = 0; k < 4; k++) {
        float bb = b1s[lane + 32 * k];
        acc[k][0] = bb; acc[k][1] = bb;
    }
    #pragma unroll
    for (int c = 0; c < Cc; c++) {
        float yv0 = ys[tokbase * 33 + c];
        float yv1 = ys[(tokbase + 1) * 33 + c];
        #pragma unroll
        for (int k = 0; k < 4; k++) {
            float wv = W1T[c * 129 + lane + 32 * k];
            acc[k][0] += yv0 * wv;
            acc[k][1] += yv1 * wv;
        }
    }
    #pragma unroll
    for (int k = 0; k < 4; k++) {
        h1s[tokbase * 132 + lane + 32 * k]       = fmaxf(acc[k][0], 0.f);
        h1s[(tokbase + 1) * 132 + lane + 32 * k] = fmaxf(acc[k][1], 0.f);
    }
    __syncwarp();

    float a2[2] = {0.f, 0.f};
    #pragma unroll 4
    for (int h = 0; h < Hh; h++) {
        float wv = W2p[lane * 129 + h];
        a2[0] += h1s[tokbase * 132 + h] * wv;
        a2[1] += h1s[(tokbase + 1) * 132 + h] * wv;
    }

    #pragma unroll
    for (int tk = 0; tk < 2; tk++) {
        int tok = tokbase + tk;
        int t = t0 + tok;
        float z = ys[tok * 33 + lane] + a2[tk] + b2s[lane];
        float sum = z;
        #pragma unroll
        for (int off = 16; off; off >>= 1)
            sum += __shfl_xor_sync(0xffffffffu, sum, off);
        float mean = sum * (1.f / Cc);
        float d = z - mean;
        float vv = d * d;
        #pragma unroll
        for (int off = 16; off; off >>= 1)
            vv += __shfl_xor_sync(0xffffffffu, vv, off);
        float rstd = rsqrtf(vv * (1.f / Cc) + 1e-14f);
        y2[(size_t)b * Cc * Tt + (size_t)lane * Tt + t] = d * rstd * g2s[lane] + be2s[lane];
    }
}

// ---------------------------------------------------------------------------
extern "C" void kernel_launch(void* const* d_in, const int* in_sizes, int n_in,
                              void* d_out, int out_size) {
    (void)in_sizes; (void)n_in; (void)out_size;
    const float* x   = (const float*)d_in[0];
    const float* Wt  = (const float*)d_in[1];
    const float* Wx  = (const float*)d_in[2];
    const float* bh  = (const float*)d_in[3];
    const float* Wa  = (const float*)d_in[4];
    const float* ba  = (const float*)d_in[5];
    const float* g1  = (const float*)d_in[6];
    const float* be1 = (const float*)d_in[7];
    const float* W1  = (const float*)d_in[8];
    const float* b1  = (const float*)d_in[9];
    const float* W2  = (const float*)d_in[10];
    const float* b2  = (const float*)d_in[11];
    const float* g2  = (const float*)d_in[12];
    const float* be2 = (const float*)d_in[13];

    float* out = (float*)d_out;
    float* y2  = out;                    // (B,C,T) = 131072 floats
    float* a   = out + Bq * Cc * Tt;     // (B,T,T) = 4194304 floats

    cudaFuncSetAttribute(k_fused, cudaFuncAttributeMaxDynamicSharedMemorySize, SMEM_FUSED);

    k_prep <<<Bq * (Tt / 8), 256>>>(x, Wt, Wx, bh);
    k_fused<<<Bq * (Tt / 8), 128, SMEM_FUSED>>>(x, a, Wa, ba, g1, be1,
                                                W1, b1, W2, b2, g2, be2, y2);
}